// round 15
// baseline (speedup 1.0000x reference)
#include <cuda_runtime.h>
#include <cstdint>

// out[b,i,j,c] = sum_k exp(-2(li-x0k)^2)*exp(-2(lj-x1k)^2)*Yb[k,c]
// GEMM: C[64 x 640] = A[64 x 1024] * Z[1024 x 640], bf16 mma m16n8k16.
// Warp = (slab-pair, nc-half, k-quarter): each Z frag feeds 2 mmas.
#define NB    16
#define NN    1024
#define STEP  (6.0f / 63.0f)
#define EX2C  (-2.885390081777927f)   // -2*log2(e)

// A frags: u32 idx = b*32768 + kstep*512 + slab*128 + lane*4 + q
__device__ __align__(16) uint32_t g_Aperm[NB * 64 * 4 * 32 * 4];

__device__ __forceinline__ float ex2f(float x) {
    float r; asm("ex2.approx.ftz.f32 %0, %1;" : "=f"(r) : "f"(x)); return r;
}
__device__ __forceinline__ uint32_t pack_bf16(float lo, float hi) {
    uint32_t d;
    asm("cvt.rn.bf16x2.f32 %0, %1, %2;" : "=r"(d) : "f"(hi), "f"(lo));
    return d;
}
#define MMA_BF16(d, a, bb) \
    asm volatile("mma.sync.aligned.m16n8k16.row.col.f32.bf16.bf16.f32 " \
        "{%0,%1,%2,%3}, {%4,%5,%6,%7}, {%8,%9}, {%0,%1,%2,%3};" \
        : "+f"(d[0]), "+f"(d[1]), "+f"(d[2]), "+f"(d[3]) \
        : "r"(a.x), "r"(a.y), "r"(a.z), "r"(a.w), "r"(bb.x), "r"(bb.y))
#define GROUP_BAR(id) \
    asm volatile("bar.sync %0, 256;" :: "r"(id) : "memory")

// ---------- prep: A frags + grid coords (512 CTAs) ----------
__global__ __launch_bounds__(256)
void rkhs_prep_kernel(const float* __restrict__ X, float* __restrict__ out)
{
    int tid = blockIdx.x * blockDim.x + threadIdx.x;
    if (tid < 4096) {
        out[tid * 2 + 0] = -3.0f + (float)(tid >> 6) * STEP;
        out[tid * 2 + 1] = -3.0f + (float)(tid & 63) * STEP;
    }
    int q     = tid & 3;
    int lane  = (tid >> 2) & 31;
    int kstep = (tid >> 7) & 63;
    int b     = tid >> 13;

    int kb = kstep * 16 + ((lane & 3) << 1) + ((q >> 1) << 3);
    float4 xx = *(const float4*)(X + (size_t)(b * NN + kb) * 2);
    int rbase = (lane >> 2) + ((q & 1) << 3);
    uint32_t* dst = g_Aperm + (b * 32768 + kstep * 512 + lane * 4 + q);
#pragma unroll
    for (int slab = 0; slab < 4; ++slab) {
        float li = -3.0f + (float)(slab * 16 + rbase) * STEP;
        float d0 = li - xx.x;
        float d1 = li - xx.z;
        dst[slab * 128] = pack_bf16(ex2f(d0 * d0 * EX2C), ex2f(d1 * d1 * EX2C));
    }
}

// ---------- main: grid 256 = (b,jt), 512 thr = 2 K-groups ----------
#define ZSLOTS (64 * 5 * 32)      // 10240 uint2 = 81920 B

__global__ __launch_bounds__(512, 2)
void rkhs_mma_kernel(const float* __restrict__ X, const float* __restrict__ Y,
                     float* __restrict__ out)
{
    extern __shared__ __align__(16) uint2 sZ[];   // [kstep*5+nc][32]

    const int bx = blockIdx.x;
    const int jt = bx & 15;
    const int b  = bx >> 4;
    const int t  = threadIdx.x;

    const int ks = t >> 8;            // K-group 0/1
    const int tl = t & 255;

    // ===== Phase 1: build THIS group's Z half; 1 jl-pair item/thread =====
    {
        const float* yb = Y + (size_t)b * (NN * 8);
        int jlp   = tl & 1;                 // jl pair: {2*jlp, 2*jlp+1}
        int q     = (tl >> 1) & 3;
        int kstep = ks * 32 + (tl >> 3);
        int klo   = kstep * 16 + q * 2;     // k's: klo, klo+1, klo+8, klo+9

        float4 xA = *(const float4*)(X + (size_t)(b * NN + klo) * 2);
        float4 xB = *(const float4*)(X + (size_t)(b * NN + klo + 8) * 2);

        const float4* y0p = (const float4*)(yb + (size_t)klo * 8);
        float4 y0a = y0p[0],  y0b = y0p[1];
        float4 y1a = y0p[2],  y1b = y0p[3];
        float4 y8a = y0p[16], y8b = y0p[17];
        float4 y9a = y0p[18], y9b = y0p[19];

        float Y0[8] = {y0a.x, y0a.y, y0a.z, y0a.w, y0b.x, y0b.y, y0b.z, y0b.w};
        float Y1[8] = {y1a.x, y1a.y, y1a.z, y1a.w, y1b.x, y1b.y, y1b.z, y1b.w};
        float Y8[8] = {y8a.x, y8a.y, y8a.z, y8a.w, y8b.x, y8b.y, y8b.z, y8b.w};
        float Y9[8] = {y9a.x, y9a.y, y9a.z, y9a.w, y9b.x, y9b.y, y9b.z, y9b.w};

        uint2* zk = sZ + (size_t)kstep * 5 * 32 + q;
#pragma unroll
        for (int jv = 0; jv < 2; ++jv) {
            int jl = jlp * 2 + jv;
            float lj = -3.0f + (float)(jt * 4 + jl) * STEP;
            float dA0 = lj - xA.y, dA1 = lj - xA.w;
            float dB0 = lj - xB.y, dB1 = lj - xB.w;
            float e0 = ex2f(dA0 * dA0 * EX2C);
            float e1 = ex2f(dA1 * dA1 * EX2C);
            float e8 = ex2f(dB0 * dB0 * EX2C);
            float e9 = ex2f(dB1 * dB1 * EX2C);

            int nbase = jl * 10;
#pragma unroll
            for (int c = 0; c < 10; ++c) {
                int n  = nbase + c;
                int nc = n >> 3;
                int r  = n & 7;
                uint2 z;
                if (c == 0) {
                    z.x = pack_bf16(e0, e1);
                    z.y = pack_bf16(e8, e9);
                } else if (c == 9) {
                    z.x = 0u; z.y = 0u;
                } else {
                    z.x = pack_bf16(e0 * Y0[c - 1], e1 * Y1[c - 1]);
                    z.y = pack_bf16(e8 * Y8[c - 1], e9 * Y9[c - 1]);
                }
                zk[nc * 32 + r * 4] = z;
            }
        }
    }
    GROUP_BAR(1 + ks);                // our Z half is ready

    // ===== Phase 2: mma mainloop; warp = (sp, nh, kq), M=32 per warp =====
    const int lane = tl & 31;
    const int wid  = tl >> 5;
    const int sp   = wid & 1;           // slabs 2sp, 2sp+1
    const int nh   = (wid >> 1) & 1;
    const int kq   = wid >> 2;          // k-quarter (16 ksteps)
    const int nc0  = nh * 3;
    const int ncnt = nh ? 2 : 3;
    const int kbase = ks * 32 + kq * 16;

    float accA[3][4], accB[3][4];
#pragma unroll
    for (int a = 0; a < 3; ++a)
#pragma unroll
        for (int r = 0; r < 4; ++r) { accA[a][r] = 0.0f; accB[a][r] = 0.0f; }

    const uint4* pA0 = (const uint4*)g_Aperm + (size_t)b * 8192
                       + kbase * 128 + (sp * 2) * 32 + lane;
    const uint4* pA1 = pA0 + 32;        // slab 2sp+1
    const uint2* zb  = sZ + (size_t)(kbase * 5 + nc0) * 32 + lane;

    uint4 a0 = __ldg(pA0), a1 = __ldg(pA1);
#pragma unroll
    for (int k16 = 0; k16 < 16; ++k16) {
        uint4 a0n, a1n;
        if (k16 < 15) {
            a0n = __ldg(pA0 + (k16 + 1) * 128);
            a1n = __ldg(pA1 + (k16 + 1) * 128);
        }
        uint2 zf[3];
#pragma unroll
        for (int cc = 0; cc < 3; ++cc)
            if (cc < ncnt)
                zf[cc] = zb[(k16 * 5 + cc) * 32];
#pragma unroll
        for (int cc = 0; cc < 3; ++cc) {
            if (cc < ncnt) {
                MMA_BF16(accA[cc], a0, zf[cc]);
                MMA_BF16(accB[cc], a1, zf[cc]);
            }
        }
        a0 = a0n; a1 = a1n;
    }

    // ===== epilogue: 4 partial buffers (ks,kq), reduce, normalize, store =====
    __syncthreads();                  // all Z reads done; alias sZ
    float* sD = (float*)sZ;           // 4 buffers x 2560 floats = 40KB
    {
        float* buf = sD + (ks * 2 + kq) * 2560;
#pragma unroll
        for (int cc = 0; cc < 3; ++cc) {
            if (cc < ncnt) {
                *(float4*)(buf + (((nc0 + cc) * 4 + sp * 2) * 32 + lane) * 4) =
                    make_float4(accA[cc][0], accA[cc][1], accA[cc][2], accA[cc][3]);
                *(float4*)(buf + (((nc0 + cc) * 4 + sp * 2 + 1) * 32 + lane) * 4) =
                    make_float4(accB[cc][0], accB[cc][1], accB[cc][2], accB[cc][3]);
            }
        }
    }
    __syncthreads();

#pragma unroll
    for (int rep = 0; rep < 5; ++rep) {
        int o = t + rep * 512;
        if (o < 2304) {
            int i   = o / 36;
            int rem = o - i * 36;
            int j   = rem / 9;
            int c   = rem - j * 9;
            int sl = i >> 4, rr = i & 15, half = rr >> 3, r8 = rr & 7;
            int col  = j * 10 + c;
            int idx  = (((col >> 3) * 4 + sl) * 32 + r8 * 4 + ((col & 7) >> 1)) * 4
                       + half * 2 + (col & 1);
            int colD = j * 10;
            int idxD = (((colD >> 3) * 4 + sl) * 32 + r8 * 4 + ((colD & 7) >> 1)) * 4
                       + half * 2 + (colD & 1);
            float dens = (sD[idxD] + sD[2560 + idxD])
                       + (sD[5120 + idxD] + sD[7680 + idxD]);
            float num  = (sD[idx] + sD[2560 + idx])
                       + (sD[5120 + idx] + sD[7680 + idx]);
            float v = (c == 0) ? dens : num / (dens + 1e-6f);
            out[8192 + (size_t)(b * 4096 + i * 64 + jt * 4 + j) * 9 + c] = v;
        }
    }
}

extern "C" void kernel_launch(void* const* d_in, const int* in_sizes, int n_in,
                              void* d_out, int out_size)
{
    const float* X = (const float*)d_in[0];
    const float* Y = (const float*)d_in[1];
    float* out = (float*)d_out;

    const int zbytes = ZSLOTS * (int)sizeof(uint2);   // 81920
    cudaFuncSetAttribute(rkhs_mma_kernel,
                         cudaFuncAttributeMaxDynamicSharedMemorySize, zbytes);

    rkhs_prep_kernel<<<512, 256>>>(X, out);
    rkhs_mma_kernel<<<256, 512, zbytes>>>(X, Y, out);
}